// round 5
// baseline (speedup 1.0000x reference)
#include <cuda_runtime.h>

#define BB 2
#define NPTS 3000
#define CH 128
#define NLAYER 6
#define MTOT (BB*NPTS)

typedef unsigned long long u64;

// ---------------- scratch (static device allocations) ----------------
__device__ __align__(16) float g_x [MTOT*CH];
__device__ __align__(16) float g_t [MTOT*CH];
__device__ __align__(16) float g_qb[MTOT*CH];
__device__ __align__(16) float g_kb[MTOT*CH];
__device__ __align__(16) float g_vb[MTOT*CH];
__device__ __align__(16) float g_ab[MTOT*CH];
__device__ __align__(16) float g_u1[MTOT*64];
__device__ __align__(16) float g_u2[MTOT*64];
__device__ float g_sum[CH];
__device__ float g_sq[CH];
__device__ float g_scale[CH];
__device__ float g_shift[CH];

// ---------------- packed f32x2 helpers ----------------
__device__ __forceinline__ u64 pack2(float lo, float hi) {
    u64 r; asm("mov.b64 %0, {%1, %2};" : "=l"(r) : "f"(lo), "f"(hi)); return r;
}
__device__ __forceinline__ void fma2(u64 &d, u64 a, u64 b) {
    asm("fma.rn.f32x2 %0, %1, %2, %0;" : "+l"(d) : "l"(a), "l"(b));
}
__device__ __forceinline__ u64 mul2(u64 a, u64 b) {
    u64 r; asm("mul.rn.f32x2 %0, %1, %2;" : "=l"(r) : "l"(a), "l"(b)); return r;
}
__device__ __forceinline__ float2 unpack2(u64 a) {
    float lo, hi; asm("mov.b64 {%0, %1}, %2;" : "=f"(lo), "=f"(hi) : "l"(a));
    return make_float2(lo, hi);
}

// ---------------- init embedding: x[m][c] = initW[c][0:6] . corr[m][0:6] + b[c] ----------------
__global__ void k_init(const float* __restrict__ cp, const float* __restrict__ W,
                       const float* __restrict__ b) {
    int idx = blockIdx.x * blockDim.x + threadIdx.x;
    if (idx >= MTOT * CH) return;
    int m = idx >> 7, c = idx & 127;
    const float* r = cp + m * 6;
    const float* w = W + c * 6;
    float acc = b[c];
#pragma unroll
    for (int j = 0; j < 6; j++) acc += w[j] * r[j];
    g_x[idx] = acc;
}

// ---------------- generic pointwise-conv GEMM: out[m][o] = A[m][:K] . W[o][:K] + bias[o] (+=) ----
// BM=64, BO=64, BK=16, 256 threads, 4x4 microtile.
__global__ void __launch_bounds__(256) k_gemm(const float* __restrict__ A,
                                              const float* __restrict__ W,
                                              const float* __restrict__ bias,
                                              float* __restrict__ out,
                                              int K, int O, int acc_flag) {
    __shared__ float As[16][64];
    __shared__ float Ws[16][64];
    const int m0 = blockIdx.x * 64;
    const int o0 = blockIdx.y * 64;
    const int tid = threadIdx.x;
    const int tx = tid & 15, ty = tid >> 4;
    const int lr = tid >> 2;          // row 0..63 for loads
    const int lk = (tid & 3) << 2;    // k offset 0,4,8,12

    float acc[4][4];
#pragma unroll
    for (int j = 0; j < 4; j++)
#pragma unroll
        for (int l = 0; l < 4; l++) acc[j][l] = 0.f;

    for (int kb = 0; kb < K; kb += 16) {
        float4 av = make_float4(0.f, 0.f, 0.f, 0.f);
        if (m0 + lr < MTOT) av = *(const float4*)(A + (size_t)(m0 + lr) * K + kb + lk);
        float4 wv = *(const float4*)(W + (size_t)(o0 + lr) * K + kb + lk);
        As[lk + 0][lr] = av.x; As[lk + 1][lr] = av.y; As[lk + 2][lr] = av.z; As[lk + 3][lr] = av.w;
        Ws[lk + 0][lr] = wv.x; Ws[lk + 1][lr] = wv.y; Ws[lk + 2][lr] = wv.z; Ws[lk + 3][lr] = wv.w;
        __syncthreads();
#pragma unroll
        for (int k = 0; k < 16; k++) {
            float4 a = *(const float4*)&As[k][ty * 4];
            float4 w = *(const float4*)&Ws[k][tx * 4];
            float aa[4] = {a.x, a.y, a.z, a.w};
            float ww[4] = {w.x, w.y, w.z, w.w};
#pragma unroll
            for (int j = 0; j < 4; j++)
#pragma unroll
                for (int l = 0; l < 4; l++) acc[j][l] += aa[j] * ww[l];
        }
        __syncthreads();
    }
#pragma unroll
    for (int j = 0; j < 4; j++) {
        int m = m0 + ty * 4 + j;
        if (m >= MTOT) continue;
#pragma unroll
        for (int l = 0; l < 4; l++) {
            int o = o0 + tx * 4 + l;
            float v = acc[j][l] + bias[o];
            if (acc_flag) v += out[(size_t)m * O + o];
            out[(size_t)m * O + o] = v;
        }
    }
}

// ---------------- BN helpers ----------------
__global__ void k_zero() {
    int t = threadIdx.x;
    g_sum[t] = 0.f; g_sq[t] = 0.f;
}

__global__ void k_stats(const float* __restrict__ t, int O) {
    int c = threadIdx.x;  // blockDim.x == O
    int chunk = (MTOT + gridDim.x - 1) / gridDim.x;
    int m0 = blockIdx.x * chunk;
    int m1 = m0 + chunk; if (m1 > MTOT) m1 = MTOT;
    float s = 0.f, q = 0.f;
    for (int m = m0; m < m1; m++) {
        float v = t[(size_t)m * O + c];
        s += v; q += v * v;
    }
    atomicAdd(&g_sum[c], s);
    atomicAdd(&g_sq[c], q);
}

__global__ void k_bnfin(const float* __restrict__ g, const float* __restrict__ beta, int O) {
    int c = threadIdx.x;
    if (c >= O) return;
    float mean = g_sum[c] * (1.f / (float)MTOT);
    float var  = g_sq[c] * (1.f / (float)MTOT) - mean * mean;
    float sc = g[c] * rsqrtf(var + 1e-5f);
    g_scale[c] = sc;
    g_shift[c] = beta[c] - mean * sc;
}

__global__ void k_bnrelu(const float* __restrict__ t, float* __restrict__ out, int O) {
    int idx = blockIdx.x * blockDim.x + threadIdx.x;
    if (idx >= MTOT * O) return;
    int c = idx & (O - 1);
    float v = t[idx] * g_scale[c] + g_shift[c];
    out[idx] = v > 0.f ? v : 0.f;
}

// ---------------- fused attention: O = softmax(sc * scale * QK^T) V ----------------
// Block: 64 queries x all keys, 256 threads (16x16), KV tiles of 64.
// sc(o,i) = max(0, 1 - (||src_o-src_i|| - ||tgt_o-tgt_i||)^2) computed on the fly.
__global__ void __launch_bounds__(256, 1) k_attn(const float* __restrict__ Q,
                                                 const float* __restrict__ K,
                                                 const float* __restrict__ V,
                                                 const float* __restrict__ src,
                                                 const float* __restrict__ tgt,
                                                 float* __restrict__ out) {
    extern __shared__ float smx[];
    float* Qs  = smx;              // [64][128]
    float* Ks  = Qs + 64 * 128;    // [64][128]
    float* Vs  = Ks + 64 * 128;    // [64][128]
    float* Ps  = Vs + 64 * 128;    // [64][65] padded
    float* kcs = Ps + 64 * 65;     // key src coords [64][3]
    float* kct = kcs + 64 * 3;     // key tgt coords [64][3]

    const int b = blockIdx.y;
    const int q0 = blockIdx.x * 64;
    const int tid = threadIdx.x;
    const int tx = tid & 15, ty = tid >> 4;

    const float* Qg = Q + (size_t)b * NPTS * CH;
    const float* Kg = K + (size_t)b * NPTS * CH;
    const float* Vg = V + (size_t)b * NPTS * CH;
    const float* sg = src + (size_t)b * NPTS * 3;
    const float* tg = tgt + (size_t)b * NPTS * 3;

    // stage Q tile
    for (int e = tid; e < 64 * 32; e += 256) {
        int r = e >> 5, c4 = (e & 31) << 2;
        float4 v = make_float4(0.f, 0.f, 0.f, 0.f);
        if (q0 + r < NPTS) v = *(const float4*)(Qg + (size_t)(q0 + r) * CH + c4);
        *(float4*)(Qs + r * 128 + c4) = v;
    }

    // query coords in registers (rows ty*4 .. ty*4+3)
    float qs0[4], qs1[4], qs2[4], qt0[4], qt1[4], qt2[4];
#pragma unroll
    for (int j = 0; j < 4; j++) {
        int r = q0 + ty * 4 + j;
        if (r < NPTS) {
            qs0[j] = sg[r * 3]; qs1[j] = sg[r * 3 + 1]; qs2[j] = sg[r * 3 + 2];
            qt0[j] = tg[r * 3]; qt1[j] = tg[r * 3 + 1]; qt2[j] = tg[r * 3 + 2];
        } else {
            qs0[j] = qs1[j] = qs2[j] = qt0[j] = qt1[j] = qt2[j] = 0.f;
        }
    }

    float mrow[4], lrow[4];
    u64 o2[4][4];  // rows ty*4+j, channel pairs (tx*8+2l, tx*8+2l+1)
#pragma unroll
    for (int j = 0; j < 4; j++) {
        mrow[j] = -1e30f; lrow[j] = 0.f;
#pragma unroll
        for (int l = 0; l < 4; l++) o2[j][l] = 0ull;
    }
    const float scale = 0.0883883476483184f;  // 1/sqrt(128)

    for (int k0 = 0; k0 < NPTS; k0 += 64) {
        __syncthreads();  // previous tile's PV done before overwriting Ks/Vs
        for (int e = tid; e < 64 * 32; e += 256) {
            int r = e >> 5, c4 = (e & 31) << 2;
            float4 kv = make_float4(0.f, 0.f, 0.f, 0.f);
            float4 vv = make_float4(0.f, 0.f, 0.f, 0.f);
            if (k0 + r < NPTS) {
                kv = *(const float4*)(Kg + (size_t)(k0 + r) * CH + c4);
                vv = *(const float4*)(Vg + (size_t)(k0 + r) * CH + c4);
            }
            *(float4*)(Ks + r * 128 + c4) = kv;
            *(float4*)(Vs + r * 128 + c4) = vv;
        }
        if (tid < 64) {
            int ki = k0 + tid;
            if (ki < NPTS) {
                kcs[tid * 3] = sg[ki * 3]; kcs[tid * 3 + 1] = sg[ki * 3 + 1]; kcs[tid * 3 + 2] = sg[ki * 3 + 2];
                kct[tid * 3] = tg[ki * 3]; kct[tid * 3 + 1] = tg[ki * 3 + 1]; kct[tid * 3 + 2] = tg[ki * 3 + 2];
            } else {
                kcs[tid * 3] = kcs[tid * 3 + 1] = kcs[tid * 3 + 2] = 0.f;
                kct[tid * 3] = kct[tid * 3 + 1] = kct[tid * 3 + 2] = 0.f;
            }
        }
        __syncthreads();

        // ---- S = Q K^T (packed f32x2 over k) ----
        u64 acc2[4][4];
#pragma unroll
        for (int j = 0; j < 4; j++)
#pragma unroll
            for (int l = 0; l < 4; l++) acc2[j][l] = 0ull;

#pragma unroll 4
        for (int k = 0; k < 128; k += 4) {
            ulonglong2 qa[4], kb2[4];
#pragma unroll
            for (int j = 0; j < 4; j++) qa[j] = *(const ulonglong2*)(Qs + (ty * 4 + j) * 128 + k);
#pragma unroll
            for (int l = 0; l < 4; l++) kb2[l] = *(const ulonglong2*)(Ks + (tx * 4 + l) * 128 + k);
#pragma unroll
            for (int j = 0; j < 4; j++)
#pragma unroll
                for (int l = 0; l < 4; l++) {
                    fma2(acc2[j][l], qa[j].x, kb2[l].x);
                    fma2(acc2[j][l], qa[j].y, kb2[l].y);
                }
        }

        // key coords for this thread's 4 columns
        float ks0[4], ks1[4], ks2[4], kt0[4], kt1[4], kt2[4];
#pragma unroll
        for (int l = 0; l < 4; l++) {
            int c = tx * 4 + l;
            ks0[l] = kcs[c * 3]; ks1[l] = kcs[c * 3 + 1]; ks2[l] = kcs[c * 3 + 2];
            kt0[l] = kct[c * 3]; kt1[l] = kct[c * 3 + 1]; kt2[l] = kct[c * 3 + 2];
        }

        float s[4][4];
#pragma unroll
        for (int j = 0; j < 4; j++)
#pragma unroll
            for (int l = 0; l < 4; l++) {
                float2 pr = unpack2(acc2[j][l]);
                float qk = (pr.x + pr.y) * scale;
                float dx = qs0[j] - ks0[l], dy = qs1[j] - ks1[l], dz = qs2[j] - ks2[l];
                float ds = sqrtf(dx * dx + dy * dy + dz * dz);
                dx = qt0[j] - kt0[l]; dy = qt1[j] - kt1[l]; dz = qt2[j] - kt2[l];
                float dt = sqrtf(dx * dx + dy * dy + dz * dz);
                float dd = ds - dt;
                float sc = fmaxf(1.f - dd * dd, 0.f);
                float val = sc * qk;
                if (k0 + tx * 4 + l >= NPTS) val = -1e30f;
                s[j][l] = val;
            }

        // ---- online softmax (row reductions across 16 tx lanes via shfl) ----
#pragma unroll
        for (int j = 0; j < 4; j++) {
            float tm = fmaxf(fmaxf(s[j][0], s[j][1]), fmaxf(s[j][2], s[j][3]));
            tm = fmaxf(tm, __shfl_xor_sync(0xffffffffu, tm, 8));
            tm = fmaxf(tm, __shfl_xor_sync(0xffffffffu, tm, 4));
            tm = fmaxf(tm, __shfl_xor_sync(0xffffffffu, tm, 2));
            tm = fmaxf(tm, __shfl_xor_sync(0xffffffffu, tm, 1));
            float mn = fmaxf(mrow[j], tm);
            float al = __expf(mrow[j] - mn);
            mrow[j] = mn;
            float p0 = __expf(s[j][0] - mn), p1 = __expf(s[j][1] - mn);
            float p2 = __expf(s[j][2] - mn), p3 = __expf(s[j][3] - mn);
            float rs = p0 + p1 + p2 + p3;
            rs += __shfl_xor_sync(0xffffffffu, rs, 8);
            rs += __shfl_xor_sync(0xffffffffu, rs, 4);
            rs += __shfl_xor_sync(0xffffffffu, rs, 2);
            rs += __shfl_xor_sync(0xffffffffu, rs, 1);
            lrow[j] = lrow[j] * al + rs;
            u64 al2 = pack2(al, al);
#pragma unroll
            for (int l = 0; l < 4; l++) o2[j][l] = mul2(o2[j][l], al2);
            float* pp = Ps + (ty * 4 + j) * 65 + tx * 4;
            pp[0] = p0; pp[1] = p1; pp[2] = p2; pp[3] = p3;
        }
        __syncthreads();  // Ps complete before PV

        // ---- O += P V (packed over channel pairs) ----
#pragma unroll 2
        for (int i = 0; i < 64; i++) {
            float pj0 = Ps[(ty * 4 + 0) * 65 + i];
            float pj1 = Ps[(ty * 4 + 1) * 65 + i];
            float pj2 = Ps[(ty * 4 + 2) * 65 + i];
            float pj3 = Ps[(ty * 4 + 3) * 65 + i];
            ulonglong2 va = *(const ulonglong2*)(Vs + i * 128 + tx * 8);
            ulonglong2 vb = *(const ulonglong2*)(Vs + i * 128 + tx * 8 + 4);
            u64 vv0 = va.x, vv1 = va.y, vv2 = vb.x, vv3 = vb.y;
            u64 pp;
            pp = pack2(pj0, pj0);
            fma2(o2[0][0], pp, vv0); fma2(o2[0][1], pp, vv1); fma2(o2[0][2], pp, vv2); fma2(o2[0][3], pp, vv3);
            pp = pack2(pj1, pj1);
            fma2(o2[1][0], pp, vv0); fma2(o2[1][1], pp, vv1); fma2(o2[1][2], pp, vv2); fma2(o2[1][3], pp, vv3);
            pp = pack2(pj2, pj2);
            fma2(o2[2][0], pp, vv0); fma2(o2[2][1], pp, vv1); fma2(o2[2][2], pp, vv2); fma2(o2[2][3], pp, vv3);
            pp = pack2(pj3, pj3);
            fma2(o2[3][0], pp, vv0); fma2(o2[3][1], pp, vv1); fma2(o2[3][2], pp, vv2); fma2(o2[3][3], pp, vv3);
        }
    }

    // epilogue: normalize and write
#pragma unroll
    for (int j = 0; j < 4; j++) {
        int r = q0 + ty * 4 + j;
        if (r >= NPTS) continue;
        float inv = 1.f / lrow[j];
        float* op = out + ((size_t)b * NPTS + r) * CH + tx * 8;
#pragma unroll
        for (int l = 0; l < 4; l++) {
            float2 pr = unpack2(o2[j][l]);
            op[l * 2]     = pr.x * inv;
            op[l * 2 + 1] = pr.y * inv;
        }
    }
}

// ---------------- final: L2-normalize features (transposed write) + confidence MLP ------------
__global__ void __launch_bounds__(256) k_final(const float* __restrict__ c1W, const float* __restrict__ c1b,
                                               const float* __restrict__ c2W, const float* __restrict__ c2b,
                                               const float* __restrict__ c3W, const float* __restrict__ c3b,
                                               float* __restrict__ outConf, float* __restrict__ outFeat) {
    __shared__ float xs[32][129];
    __shared__ float nrm[32];
    __shared__ float h1s[32][33];
    __shared__ float h2s[32][33];
    __shared__ float part[32][8];
    const int m0 = blockIdx.x * 32;
    const int tid = threadIdx.x;

    for (int e = tid; e < 32 * 32; e += 256) {
        int p = e >> 5, c4 = (e & 31) << 2;
        float4 v = make_float4(0.f, 0.f, 0.f, 0.f);
        if (m0 + p < MTOT) v = *(const float4*)(g_x + (size_t)(m0 + p) * CH + c4);
        xs[p][c4] = v.x; xs[p][c4 + 1] = v.y; xs[p][c4 + 2] = v.z; xs[p][c4 + 3] = v.w;
    }
    __syncthreads();

    const int p = tid >> 3, q = tid & 7;
    float ss = 0.f;
    for (int c = q; c < 128; c += 8) { float v = xs[p][c]; ss += v * v; }
    part[p][q] = ss;
    __syncthreads();
    if (q == 0) {
        float t = 0.f;
#pragma unroll
        for (int i = 0; i < 8; i++) t += part[p][i];
        nrm[p] = fmaxf(sqrtf(t), 1e-12f);
    }
    __syncthreads();

    // h1 = relu(c1W . x + c1b), each (p,q) computes 4 of 32 channels
    {
        float a0 = c1b[q * 4], a1 = c1b[q * 4 + 1], a2 = c1b[q * 4 + 2], a3 = c1b[q * 4 + 3];
        const float* w0 = c1W + (q * 4 + 0) * 128;
        const float* w1 = c1W + (q * 4 + 1) * 128;
        const float* w2 = c1W + (q * 4 + 2) * 128;
        const float* w3 = c1W + (q * 4 + 3) * 128;
        for (int c = 0; c < 128; c++) {
            float xv = xs[p][c];
            a0 += w0[c] * xv; a1 += w1[c] * xv; a2 += w2[c] * xv; a3 += w3[c] * xv;
        }
        h1s[p][q * 4]     = fmaxf(a0, 0.f);
        h1s[p][q * 4 + 1] = fmaxf(a1, 0.f);
        h1s[p][q * 4 + 2] = fmaxf(a2, 0.f);
        h1s[p][q * 4 + 3] = fmaxf(a3, 0.f);
    }
    __syncthreads();
    // h2 = relu(c2W . h1 + c2b)
    {
        float a0 = c2b[q * 4], a1 = c2b[q * 4 + 1], a2 = c2b[q * 4 + 2], a3 = c2b[q * 4 + 3];
        const float* w0 = c2W + (q * 4 + 0) * 32;
        const float* w1 = c2W + (q * 4 + 1) * 32;
        const float* w2 = c2W + (q * 4 + 2) * 32;
        const float* w3 = c2W + (q * 4 + 3) * 32;
        for (int c = 0; c < 32; c++) {
            float hv = h1s[p][c];
            a0 += w0[c] * hv; a1 += w1[c] * hv; a2 += w2[c] * hv; a3 += w3[c] * hv;
        }
        h2s[p][q * 4]     = fmaxf(a0, 0.f);
        h2s[p][q * 4 + 1] = fmaxf(a1, 0.f);
        h2s[p][q * 4 + 2] = fmaxf(a2, 0.f);
        h2s[p][q * 4 + 3] = fmaxf(a3, 0.f);
    }
    __syncthreads();
    if (q == 0 && m0 + p < MTOT) {
        float s = c3b[0];
        for (int c = 0; c < 32; c++) s += c3W[c] * h2s[p][c];
        outConf[m0 + p] = s;  // [B,N] flattened == m
    }
    // normed features, [B,C,N] layout (transposed, coalesced over n)
    for (int e = tid; e < 32 * 128; e += 256) {
        int c = e >> 5, i = e & 31;
        int m = m0 + i;
        if (m < MTOT) {
            int b = m / NPTS, n = m - b * NPTS;
            outFeat[((size_t)b * CH + c) * NPTS + n] = xs[i][c] / nrm[i];
        }
    }
}

// ---------------- host orchestration ----------------
#define ATTN_SMEM ((3 * 64 * 128 + 64 * 65 + 2 * 64 * 3) * (int)sizeof(float))

extern "C" void kernel_launch(void* const* d_in, const int* in_sizes, int n_in,
                              void* d_out, int out_size) {
    const float* corr   = (const float*)d_in[0];
    const float* src    = (const float*)d_in[1];
    const float* tgt    = (const float*)d_in[2];
    const float* initW  = (const float*)d_in[3];
    const float* initb  = (const float*)d_in[4];
    const float* pcnW   = (const float*)d_in[5];
    const float* pcnb   = (const float*)d_in[6];
    const float* pcng   = (const float*)d_in[7];
    const float* pcnbt  = (const float*)d_in[8];
    const float* qW     = (const float*)d_in[9];
    const float* qb     = (const float*)d_in[10];
    const float* kW     = (const float*)d_in[11];
    const float* kb     = (const float*)d_in[12];
    const float* vW     = (const float*)d_in[13];
    const float* vb     = (const float*)d_in[14];
    const float* m1W    = (const float*)d_in[15];
    const float* m1b    = (const float*)d_in[16];
    const float* m1g    = (const float*)d_in[17];
    const float* m1bt   = (const float*)d_in[18];
    const float* m2W    = (const float*)d_in[19];
    const float* m2b    = (const float*)d_in[20];
    const float* m2g    = (const float*)d_in[21];
    const float* m2bt   = (const float*)d_in[22];
    const float* m3W    = (const float*)d_in[23];
    const float* m3b    = (const float*)d_in[24];
    const float* c1W    = (const float*)d_in[25];
    const float* c1b    = (const float*)d_in[26];
    const float* c2W    = (const float*)d_in[27];
    const float* c2b    = (const float*)d_in[28];
    const float* c3W    = (const float*)d_in[29];
    const float* c3b    = (const float*)d_in[30];

    float* out = (float*)d_out;
    float* outConf = out;            // [B,N]  = 6000 floats
    float* outFeat = out + MTOT;     // [B,C,N] = 768000 floats

    float *px, *pt, *pq, *pk, *pv, *pa, *pu1, *pu2;
    cudaGetSymbolAddress((void**)&px,  g_x);
    cudaGetSymbolAddress((void**)&pt,  g_t);
    cudaGetSymbolAddress((void**)&pq,  g_qb);
    cudaGetSymbolAddress((void**)&pk,  g_kb);
    cudaGetSymbolAddress((void**)&pv,  g_vb);
    cudaGetSymbolAddress((void**)&pa,  g_ab);
    cudaGetSymbolAddress((void**)&pu1, g_u1);
    cudaGetSymbolAddress((void**)&pu2, g_u2);

    cudaFuncSetAttribute(k_attn, cudaFuncAttributeMaxDynamicSharedMemorySize, ATTN_SMEM);

    const int GM = (MTOT + 63) / 64;  // 94

    k_init<<<(MTOT * CH + 255) / 256, 256>>>(corr, initW, initb);

    for (int i = 0; i < NLAYER; i++) {
        // PointCN: x = relu(bn(conv(x)))
        k_gemm<<<dim3(GM, 2), 256>>>(px, pcnW + i * CH * CH, pcnb + i * CH, pt, 128, 128, 0);
        k_zero<<<1, 128>>>();
        k_stats<<<60, 128>>>(pt, 128);
        k_bnfin<<<1, 128>>>(pcng + i * CH, pcnbt + i * CH, 128);
        k_bnrelu<<<(MTOT * 128 + 255) / 256, 256>>>(pt, px, 128);

        // Q, K, V
        k_gemm<<<dim3(GM, 2), 256>>>(px, qW + i * CH * CH, qb + i * CH, pq, 128, 128, 0);
        k_gemm<<<dim3(GM, 2), 256>>>(px, kW + i * CH * CH, kb + i * CH, pk, 128, 128, 0);
        k_gemm<<<dim3(GM, 2), 256>>>(px, vW + i * CH * CH, vb + i * CH, pv, 128, 128, 0);

        // fused spatial-compat attention
        k_attn<<<dim3((NPTS + 63) / 64, BB), 256, ATTN_SMEM>>>(pq, pk, pv, src, tgt, pa);

        // msg MLP: m1 -> bn relu -> m2 -> bn relu -> m3 (+ residual into x)
        k_gemm<<<dim3(GM, 1), 256>>>(pa, m1W + i * 64 * 128, m1b + i * 64, pt, 128, 64, 0);
        k_zero<<<1, 128>>>();
        k_stats<<<60, 64>>>(pt, 64);
        k_bnfin<<<1, 64>>>(m1g + i * 64, m1bt + i * 64, 64);
        k_bnrelu<<<(MTOT * 64 + 255) / 256, 256>>>(pt, pu1, 64);

        k_gemm<<<dim3(GM, 1), 256>>>(pu1, m2W + i * 64 * 64, m2b + i * 64, pt, 64, 64, 0);
        k_zero<<<1, 128>>>();
        k_stats<<<60, 64>>>(pt, 64);
        k_bnfin<<<1, 64>>>(m2g + i * 64, m2bt + i * 64, 64);
        k_bnrelu<<<(MTOT * 64 + 255) / 256, 256>>>(pt, pu2, 64);

        k_gemm<<<dim3(GM, 2), 256>>>(pu2, m3W + i * 128 * 64, m3b + i * CH, px, 64, 128, 1);
    }

    k_final<<<(MTOT + 31) / 32, 256>>>(c1W, c1b, c2W, c2b, c3W, c3b, outConf, outFeat);
}

// round 15
// speedup vs baseline: 1.7899x; 1.7899x over previous
#include <cuda_runtime.h>

#define BB 2
#define NPTS 3000
#define CH 128
#define NLAYER 6
#define MTOT (BB*NPTS)

#define KP_PAD 66   // u64 columns per kp-row of pair-major K tile (even -> 16B-aligned rows)

typedef unsigned long long u64;

// ---------------- scratch (static device allocations) ----------------
__device__ __align__(16) float g_x [MTOT*CH];
__device__ __align__(16) float g_t [MTOT*CH];
__device__ __align__(16) float g_qb[MTOT*CH];
__device__ __align__(16) float g_kb[MTOT*CH];
__device__ __align__(16) float g_vb[MTOT*CH];
__device__ __align__(16) float g_ab[MTOT*CH];
__device__ __align__(16) float g_u1[MTOT*64];
__device__ __align__(16) float g_u2[MTOT*64];
__device__ float g_scale[CH];
__device__ float g_shift[CH];

// ---------------- packed f32x2 helpers ----------------
__device__ __forceinline__ u64 pack2(float lo, float hi) {
    u64 r; asm("mov.b64 %0, {%1, %2};" : "=l"(r) : "f"(lo), "f"(hi)); return r;
}
__device__ __forceinline__ void fma2(u64 &d, u64 a, u64 b) {
    asm("fma.rn.f32x2 %0, %1, %2, %0;" : "+l"(d) : "l"(a), "l"(b));
}
__device__ __forceinline__ u64 mul2(u64 a, u64 b) {
    u64 r; asm("mul.rn.f32x2 %0, %1, %2;" : "=l"(r) : "l"(a), "l"(b)); return r;
}
__device__ __forceinline__ float2 unpack2(u64 a) {
    float lo, hi; asm("mov.b64 {%0, %1}, %2;" : "=f"(lo), "=f"(hi) : "l"(a));
    return make_float2(lo, hi);
}

// ---------------- init embedding ----------------
__global__ void k_init(const float* __restrict__ cp, const float* __restrict__ W,
                       const float* __restrict__ b) {
    int idx = blockIdx.x * blockDim.x + threadIdx.x;
    if (idx >= MTOT * CH) return;
    int m = idx >> 7, c = idx & 127;
    const float* r = cp + m * 6;
    const float* w = W + c * 6;
    float acc = b[c];
#pragma unroll
    for (int j = 0; j < 6; j++) acc += w[j] * r[j];
    g_x[idx] = acc;
}

// ---------------- pointwise-conv GEMM: out[m][o] = A[m][:K] . W[o][:K] + bias[o] (+=) ----
__global__ void __launch_bounds__(256) k_gemm(const float* __restrict__ A,
                                              const float* __restrict__ W,
                                              const float* __restrict__ bias,
                                              float* __restrict__ out,
                                              int K, int O, int acc_flag) {
    __shared__ float As[16][64];
    __shared__ float Ws[16][64];
    const int m0 = blockIdx.x * 64;
    const int o0 = blockIdx.y * 64;
    const int tid = threadIdx.x;
    const int tx = tid & 15, ty = tid >> 4;
    const int lr = tid >> 2;
    const int lk = (tid & 3) << 2;

    float acc[4][4];
#pragma unroll
    for (int j = 0; j < 4; j++)
#pragma unroll
        for (int l = 0; l < 4; l++) acc[j][l] = 0.f;

    for (int kb = 0; kb < K; kb += 16) {
        float4 av = make_float4(0.f, 0.f, 0.f, 0.f);
        if (m0 + lr < MTOT) av = *(const float4*)(A + (size_t)(m0 + lr) * K + kb + lk);
        float4 wv = *(const float4*)(W + (size_t)(o0 + lr) * K + kb + lk);
        As[lk + 0][lr] = av.x; As[lk + 1][lr] = av.y; As[lk + 2][lr] = av.z; As[lk + 3][lr] = av.w;
        Ws[lk + 0][lr] = wv.x; Ws[lk + 1][lr] = wv.y; Ws[lk + 2][lr] = wv.z; Ws[lk + 3][lr] = wv.w;
        __syncthreads();
#pragma unroll
        for (int k = 0; k < 16; k++) {
            float4 a = *(const float4*)&As[k][ty * 4];
            float4 w = *(const float4*)&Ws[k][tx * 4];
            float aa[4] = {a.x, a.y, a.z, a.w};
            float ww[4] = {w.x, w.y, w.z, w.w};
#pragma unroll
            for (int j = 0; j < 4; j++)
#pragma unroll
                for (int l = 0; l < 4; l++) acc[j][l] += aa[j] * ww[l];
        }
        __syncthreads();
    }
#pragma unroll
    for (int j = 0; j < 4; j++) {
        int m = m0 + ty * 4 + j;
        if (m >= MTOT) continue;
#pragma unroll
        for (int l = 0; l < 4; l++) {
            int o = o0 + tx * 4 + l;
            float v = acc[j][l] + bias[o];
            if (acc_flag) v += out[(size_t)m * O + o];
            out[(size_t)m * O + o] = v;
        }
    }
}

// ---------------- deterministic two-pass BN: one block per channel ----------------
// Pass 1: mean via fixed-order tree reduce (no atomics). Pass 2: var = E[(x-mean)^2]
// (no cancellation). scale = g/sqrt(var+eps) with correctly-rounded sqrt+div.
__global__ void __launch_bounds__(256) k_bn(const float* __restrict__ t,
                                            const float* __restrict__ g,
                                            const float* __restrict__ beta,
                                            int O) {
    __shared__ float red[256];
    const int c = blockIdx.x;
    const int tid = threadIdx.x;

    float s = 0.f;
    for (int m = tid; m < MTOT; m += 256) s += t[(size_t)m * O + c];
    red[tid] = s;
    __syncthreads();
#pragma unroll
    for (int w = 128; w > 0; w >>= 1) {
        if (tid < w) red[tid] += red[tid + w];
        __syncthreads();
    }
    const float mean = red[0] * (1.f / (float)MTOT);
    __syncthreads();  // everyone has read red[0]; safe to reuse

    float v = 0.f;
    for (int m = tid; m < MTOT; m += 256) {
        float d = t[(size_t)m * O + c] - mean;
        v += d * d;
    }
    red[tid] = v;
    __syncthreads();
#pragma unroll
    for (int w = 128; w > 0; w >>= 1) {
        if (tid < w) red[tid] += red[tid + w];
        __syncthreads();
    }
    if (tid == 0) {
        float var = red[0] * (1.f / (float)MTOT);
        float sc = g[c] / sqrtf(var + 1e-5f);
        g_scale[c] = sc;
        g_shift[c] = beta[c] - mean * sc;
    }
}

__global__ void k_bnrelu(const float* __restrict__ t, float* __restrict__ out, int O) {
    int idx = blockIdx.x * blockDim.x + threadIdx.x;
    if (idx >= MTOT * O) return;
    int c = idx & (O - 1);
    float v = t[idx] * g_scale[c] + g_shift[c];
    out[idx] = v > 0.f ? v : 0.f;
}

// ---------------- fused attention: O = softmax(sc * scale * QK^T) V ----------------
// Block: 64 queries x all keys, 256 threads (16x16), KV tiles of 64.
// smem:
//   float Qs[64][128]    row-major Q tile   (QK reads are per-ty broadcasts: conflict-free)
//   u64   Kp[64][KP_PAD] pair-major K tile  (QK reads lane-contiguous: conflict-free)
//   float Vs[64][128]    row-major V tile   (PV reads lane-contiguous via channel split)
//   float Ps[64][65]
//   float kcs[64][3], kct[64][3]
#define ATTN_SMEM (64*128*4 + 64*KP_PAD*8 + 64*128*4 + 64*65*4 + 2*64*3*4)

__global__ void __launch_bounds__(256, 1) k_attn(const float* __restrict__ Q,
                                                 const float* __restrict__ K,
                                                 const float* __restrict__ V,
                                                 const float* __restrict__ src,
                                                 const float* __restrict__ tgt,
                                                 float* __restrict__ out) {
    extern __shared__ __align__(16) char smraw[];
    float* Qs  = (float*)smraw;              // [64][128]
    u64*   Kp  = (u64*)(Qs + 64 * 128);      // [64][KP_PAD]
    float* Vs  = (float*)(Kp + 64 * KP_PAD); // [64][128]
    float* Ps  = Vs + 64 * 128;              // [64][65]
    float* kcs = Ps + 64 * 65;
    float* kct = kcs + 64 * 3;

    const int b = blockIdx.y;
    const int q0 = blockIdx.x * 64;
    const int tid = threadIdx.x;
    const int tx = tid & 15, ty = tid >> 4;
    const int warp = tid >> 5, lane = tid & 31;

    const float* Qg = Q + (size_t)b * NPTS * CH;
    const float* Kg = K + (size_t)b * NPTS * CH;
    const float* Vg = V + (size_t)b * NPTS * CH;
    const float* sg = src + (size_t)b * NPTS * 3;
    const float* tg = tgt + (size_t)b * NPTS * 3;

    // stage Q tile (row-major)
    for (int e = tid; e < 64 * 32; e += 256) {
        int r = e >> 5, c4 = (e & 31) << 2;
        float4 v = make_float4(0.f, 0.f, 0.f, 0.f);
        if (q0 + r < NPTS) v = *(const float4*)(Qg + (size_t)(q0 + r) * CH + c4);
        *(float4*)(Qs + r * 128 + c4) = v;
    }

    // query coords in registers (rows ty*4 .. ty*4+3)
    float qs0[4], qs1[4], qs2[4], qt0[4], qt1[4], qt2[4];
#pragma unroll
    for (int j = 0; j < 4; j++) {
        int r = q0 + ty * 4 + j;
        if (r < NPTS) {
            qs0[j] = sg[r * 3]; qs1[j] = sg[r * 3 + 1]; qs2[j] = sg[r * 3 + 2];
            qt0[j] = tg[r * 3]; qt1[j] = tg[r * 3 + 1]; qt2[j] = tg[r * 3 + 2];
        } else {
            qs0[j] = qs1[j] = qs2[j] = qt0[j] = qt1[j] = qt2[j] = 0.f;
        }
    }

    float mrow[4], lrow[4];
    u64 o2[4][4];  // rows ty*4+j; channel pairs: l=0 ->(tx*4,+1), l=1 ->(tx*4+2,+3),
                   //                              l=2 ->(64+tx*4,+1), l=3 ->(64+tx*4+2,+3)
#pragma unroll
    for (int j = 0; j < 4; j++) {
        mrow[j] = -1e30f; lrow[j] = 0.f;
#pragma unroll
        for (int l = 0; l < 4; l++) o2[j][l] = 0ull;
    }
    const float scale = 0.0883883476483184f;  // 1/sqrt(128)

    for (int k0 = 0; k0 < NPTS; k0 += 64) {
        __syncthreads();  // previous tile fully consumed before overwriting Kp/Vs

        // ---- stage K tile pair-major: warp w owns channels [w*16, w*16+16) -> kp rows [w*8, w*8+8) ----
        for (int kk = lane; kk < 64; kk += 32) {
            float4 v0 = make_float4(0.f,0.f,0.f,0.f), v1 = v0, v2 = v0, v3 = v0;
            if (k0 + kk < NPTS) {
                const float4* p = (const float4*)(Kg + (size_t)(k0 + kk) * CH + warp * 16);
                v0 = p[0]; v1 = p[1]; v2 = p[2]; v3 = p[3];
            }
            u64* dst = Kp + (warp * 8) * KP_PAD + kk;
            dst[0 * KP_PAD] = pack2(v0.x, v0.y);
            dst[1 * KP_PAD] = pack2(v0.z, v0.w);
            dst[2 * KP_PAD] = pack2(v1.x, v1.y);
            dst[3 * KP_PAD] = pack2(v1.z, v1.w);
            dst[4 * KP_PAD] = pack2(v2.x, v2.y);
            dst[5 * KP_PAD] = pack2(v2.z, v2.w);
            dst[6 * KP_PAD] = pack2(v3.x, v3.y);
            dst[7 * KP_PAD] = pack2(v3.z, v3.w);
        }
        // ---- stage V tile (row-major) ----
        for (int e = tid; e < 64 * 32; e += 256) {
            int r = e >> 5, c4 = (e & 31) << 2;
            float4 vv = make_float4(0.f, 0.f, 0.f, 0.f);
            if (k0 + r < NPTS) vv = *(const float4*)(Vg + (size_t)(k0 + r) * CH + c4);
            *(float4*)(Vs + r * 128 + c4) = vv;
        }
        // ---- key coordinates ----
        if (tid < 64) {
            int ki = k0 + tid;
            if (ki < NPTS) {
                kcs[tid * 3] = sg[ki * 3]; kcs[tid * 3 + 1] = sg[ki * 3 + 1]; kcs[tid * 3 + 2] = sg[ki * 3 + 2];
                kct[tid * 3] = tg[ki * 3]; kct[tid * 3 + 1] = tg[ki * 3 + 1]; kct[tid * 3 + 2] = tg[ki * 3 + 2];
            } else {
                kcs[tid * 3] = kcs[tid * 3 + 1] = kcs[tid * 3 + 2] = 0.f;
                kct[tid * 3] = kct[tid * 3 + 1] = kct[tid * 3 + 2] = 0.f;
            }
        }
        __syncthreads();

        // ---- S = Q K^T : f32x2 over channel pairs, conflict-free, k ascending ----
        u64 acc2[4][4];
#pragma unroll
        for (int j = 0; j < 4; j++)
#pragma unroll
            for (int l = 0; l < 4; l++) acc2[j][l] = 0ull;

        const u64* kbase = Kp + tx * 4;
#pragma unroll 4
        for (int kp = 0; kp < 64; kp += 2) {
            ulonglong2 qa[4];
#pragma unroll
            for (int j = 0; j < 4; j++)
                qa[j] = *(const ulonglong2*)(Qs + (ty * 4 + j) * 128 + 2 * kp);  // pairs kp, kp+1
            ulonglong2 ka = *(const ulonglong2*)(kbase + kp * KP_PAD);           // keys tx*4,+1 @ pair kp
            ulonglong2 kb = *(const ulonglong2*)(kbase + kp * KP_PAD + 2);       // keys tx*4+2,+3 @ pair kp
            ulonglong2 kc = *(const ulonglong2*)(kbase + (kp + 1) * KP_PAD);     // @ pair kp+1
            ulonglong2 kd = *(const ulonglong2*)(kbase + (kp + 1) * KP_PAD + 2);
#pragma unroll
            for (int j = 0; j < 4; j++) {
                fma2(acc2[j][0], qa[j].x, ka.x);
                fma2(acc2[j][0], qa[j].y, kc.x);
                fma2(acc2[j][1], qa[j].x, ka.y);
                fma2(acc2[j][1], qa[j].y, kc.y);
                fma2(acc2[j][2], qa[j].x, kb.x);
                fma2(acc2[j][2], qa[j].y, kd.x);
                fma2(acc2[j][3], qa[j].x, kb.y);
                fma2(acc2[j][3], qa[j].y, kd.y);
            }
        }

        // key coords for this thread's 4 columns
        float ks0[4], ks1[4], ks2[4], kt0[4], kt1[4], kt2[4];
#pragma unroll
        for (int l = 0; l < 4; l++) {
            int c = tx * 4 + l;
            ks0[l] = kcs[c * 3]; ks1[l] = kcs[c * 3 + 1]; ks2[l] = kcs[c * 3 + 2];
            kt0[l] = kct[c * 3]; kt1[l] = kct[c * 3 + 1]; kt2[l] = kct[c * 3 + 2];
        }

        float s[4][4];
#pragma unroll
        for (int j = 0; j < 4; j++)
#pragma unroll
            for (int l = 0; l < 4; l++) {
                float2 pr = unpack2(acc2[j][l]);
                float qk = (pr.x + pr.y) * scale;
                float dx = qs0[j] - ks0[l], dy = qs1[j] - ks1[l], dz = qs2[j] - ks2[l];
                float ds = sqrtf(dx * dx + dy * dy + dz * dz);
                dx = qt0[j] - kt0[l]; dy = qt1[j] - kt1[l]; dz = qt2[j] - kt2[l];
                float dt = sqrtf(dx * dx + dy * dy + dz * dz);
                float dd = ds - dt;
                float sc = fmaxf(1.f - dd * dd, 0.f);
                float val = sc * qk;
                if (k0 + tx * 4 + l >= NPTS) val = -1e30f;
                s[j][l] = val;
            }

        // ---- online softmax (row reductions over 16 tx lanes) ----
#pragma unroll
        for (int j = 0; j < 4; j++) {
            float tm = fmaxf(fmaxf(s[j][0], s[j][1]), fmaxf(s[j][2], s[j][3]));
            tm = fmaxf(tm, __shfl_xor_sync(0xffffffffu, tm, 8));
            tm = fmaxf(tm, __shfl_xor_sync(0xffffffffu, tm, 4));
            tm = fmaxf(tm, __shfl_xor_sync(0xffffffffu, tm, 2));
            tm = fmaxf(tm, __shfl_xor_sync(0xffffffffu, tm, 1));
            float mn = fmaxf(mrow[j], tm);
            float al = __expf(mrow[j] - mn);
            mrow[j] = mn;
            float p0 = __expf(s[j][0] - mn), p1 = __expf(s[j][1] - mn);
            float p2 = __expf(s[j][2] - mn), p3 = __expf(s[j][3] - mn);
            float rs = p0 + p1 + p2 + p3;
            rs += __shfl_xor_sync(0xffffffffu, rs, 8);
            rs += __shfl_xor_sync(0xffffffffu, rs, 4);
            rs += __shfl_xor_sync(0xffffffffu, rs, 2);
            rs += __shfl_xor_sync(0xffffffffu, rs, 1);
            lrow[j] = lrow[j] * al + rs;
            u64 al2 = pack2(al, al);
#pragma unroll
            for (int l = 0; l < 4; l++) o2[j][l] = mul2(o2[j][l], al2);
            float* pp = Ps + (ty * 4 + j) * 65 + tx * 4;
            pp[0] = p0; pp[1] = p1; pp[2] = p2; pp[3] = p3;
        }
        __syncthreads();  // Ps complete before PV

        // ---- O += P V : channels {tx*4..+3} and {64+tx*4..+3}, conflict-free ----
#pragma unroll 2
        for (int i = 0; i < 64; i++) {
            float pj0 = Ps[(ty * 4 + 0) * 65 + i];
            float pj1 = Ps[(ty * 4 + 1) * 65 + i];
            float pj2 = Ps[(ty * 4 + 2) * 65 + i];
            float pj3 = Ps[(ty * 4 + 3) * 65 + i];
            ulonglong2 va = *(const ulonglong2*)(Vs + i * 128 + tx * 4);
            ulonglong2 vb = *(const ulonglong2*)(Vs + i * 128 + 64 + tx * 4);
            u64 pp;
            pp = pack2(pj0, pj0);
            fma2(o2[0][0], pp, va.x); fma2(o2[0][1], pp, va.y);
            fma2(o2[0][2], pp, vb.x); fma2(o2[0][3], pp, vb.y);
            pp = pack2(pj1, pj1);
            fma2(o2[1][0], pp, va.x); fma2(o2[1][1], pp, va.y);
            fma2(o2[1][2], pp, vb.x); fma2(o2[1][3], pp, vb.y);
            pp = pack2(pj2, pj2);
            fma2(o2[2][0], pp, va.x); fma2(o2[2][1], pp, va.y);
            fma2(o2[2][2], pp, vb.x); fma2(o2[2][3], pp, vb.y);
            pp = pack2(pj3, pj3);
            fma2(o2[3][0], pp, va.x); fma2(o2[3][1], pp, va.y);
            fma2(o2[3][2], pp, vb.x); fma2(o2[3][3], pp, vb.y);
        }
    }

    // ---- epilogue: normalize and write ----
#pragma unroll
    for (int j = 0; j < 4; j++) {
        int r = q0 + ty * 4 + j;
        if (r >= NPTS) continue;
        float inv = 1.f / lrow[j];
        float* op = out + ((size_t)b * NPTS + r) * CH;
        float2 a0 = unpack2(o2[j][0]);
        float2 a1 = unpack2(o2[j][1]);
        *(float4*)(op + tx * 4) = make_float4(a0.x * inv, a0.y * inv, a1.x * inv, a1.y * inv);
        float2 b0 = unpack2(o2[j][2]);
        float2 b1 = unpack2(o2[j][3]);
        *(float4*)(op + 64 + tx * 4) = make_float4(b0.x * inv, b0.y * inv, b1.x * inv, b1.y * inv);
    }
}

// ---------------- final: L2-normalize features + confidence MLP ----------------
__global__ void __launch_bounds__(256) k_final(const float* __restrict__ c1W, const float* __restrict__ c1b,
                                               const float* __restrict__ c2W, const float* __restrict__ c2b,
                                               const float* __restrict__ c3W, const float* __restrict__ c3b,
                                               float* __restrict__ outConf, float* __restrict__ outFeat) {
    __shared__ float xs[32][129];
    __shared__ float nrm[32];
    __shared__ float h1s[32][33];
    __shared__ float h2s[32][33];
    __shared__ float part[32][8];
    const int m0 = blockIdx.x * 32;
    const int tid = threadIdx.x;

    for (int e = tid; e < 32 * 32; e += 256) {
        int p = e >> 5, c4 = (e & 31) << 2;
        float4 v = make_float4(0.f, 0.f, 0.f, 0.f);
        if (m0 + p < MTOT) v = *(const float4*)(g_x + (size_t)(m0 + p) * CH + c4);
        xs[p][c4] = v.x; xs[p][c4 + 1] = v.y; xs[p][c4 + 2] = v.z; xs[p][c4 + 3] = v.w;
    }
    __syncthreads();

    const int p = tid >> 3, q = tid & 7;
    float ss = 0.f;
    for (int c = q; c < 128; c += 8) { float v = xs[p][c]; ss += v * v; }
    part[p][q] = ss;
    __syncthreads();
    if (q == 0) {
        float t = 0.f;
#pragma unroll
        for (int i = 0; i < 8; i++) t += part[p][i];
        nrm[p] = fmaxf(sqrtf(t), 1e-12f);
    }
    __syncthreads();

    {
        float a0 = c1b[q * 4], a1 = c1b[q * 4 + 1], a2 = c1b[q * 4 + 2], a3 = c1b[q * 4 + 3];
        const float* w0 = c1W + (q * 4 + 0) * 128;
        const float* w1 = c1W + (q * 4 + 1) * 128;
        const float* w2 = c1W + (q * 4 + 2) * 128;
        const float* w3 = c1W + (q * 4 + 3) * 128;
        for (int c = 0; c < 128; c++) {
            float xv = xs[p][c];
            a0 += w0[c] * xv; a1 += w1[c] * xv; a2 += w2[c] * xv; a3 += w3[c] * xv;
        }
        h1s[p][q * 4]     = fmaxf(a0, 0.f);
        h1s[p][q * 4 + 1] = fmaxf(a1, 0.f);
        h1s[p][q * 4 + 2] = fmaxf(a2, 0.f);
        h1s[p][q * 4 + 3] = fmaxf(a3, 0.f);
    }
    __syncthreads();
    {
        float a0 = c2b[q * 4], a1 = c2b[q * 4 + 1], a2 = c2b[q * 4 + 2], a3 = c2b[q * 4 + 3];
        const float* w0 = c2W + (q * 4 + 0) * 32;
        const float* w1 = c2W + (q * 4 + 1) * 32;
        const float* w2 = c2W + (q * 4 + 2) * 32;
        const float* w3 = c2W + (q * 4 + 3) * 32;
        for (int c = 0; c < 32; c++) {
            float hv = h1s[p][c];
            a0 += w0[c] * hv; a1 += w1[c] * hv; a2 += w2[c] * hv; a3 += w3[c] * hv;
        }
        h2s[p][q * 4]     = fmaxf(a0, 0.f);
        h2s[p][q * 4 + 1] = fmaxf(a1, 0.f);
        h2s[p][q * 4 + 2] = fmaxf(a2, 0.f);
        h2s[p][q * 4 + 3] = fmaxf(a3, 0.f);
    }
    __syncthreads();
    if (q == 0 && m0 + p < MTOT) {
        float s = c3b[0];
        for (int c = 0; c < 32; c++) s += c3W[c] * h2s[p][c];
        outConf[m0 + p] = s;
    }
    for (int e = tid; e < 32 * 128; e += 256) {
        int c = e >> 5, i = e & 31;
        int m = m0 + i;
        if (m < MTOT) {
            int b = m / NPTS, n = m - b * NPTS;
            outFeat[((size_t)b * CH + c) * NPTS + n] = xs[i][c] / nrm[i];
        }
    }
}

// ---------------- host orchestration ----------------
extern "C" void kernel_launch(void* const* d_in, const int* in_sizes, int n_in,
                              void* d_out, int out_size) {
    const float* corr   = (const float*)d_in[0];
    const float* src    = (const float*)d_in[1];
    const float* tgt    = (const float*)d_in[2];
    const float* initW  = (const float*)d_in[3];
    const float* initb  = (const float*)d_in[4];
    const float* pcnW   = (const float*)d_in[5];
    const float* pcnb   = (const float*)d_in[6];
    const float* pcng   = (const float*)d_in[7];
    const float* pcnbt  = (const float*)d_in[8];
    const float* qW     = (const float*)d_in[9];
    const float* qb     = (const float*)d_in[10];
    const float* kW     = (const float*)d_in[11];
    const float* kb     = (const float*)d_in[12];
    const float* vW     = (const float*)d_in[13];
    const float* vb     = (const float*)d_in[14];
    const float* m1W    = (const float*)d_in[15];
    const float* m1b    = (const float*)d_in[16];
    const float* m1g    = (const float*)d_in[17];
    const float* m1bt   = (const float*)d_in[18];
    const float* m2W    = (const float*)d_in[19];
    const float* m2b    = (const float*)d_in[20];
    const float* m2g    = (const float*)d_in[21];
    const float* m2bt   = (const float*)d_in[22];
    const float* m3W    = (const float*)d_in[23];
    const float* m3b    = (const float*)d_in[24];
    const float* c1W    = (const float*)d_in[25];
    const float* c1b    = (const float*)d_in[26];
    const float* c2W    = (const float*)d_in[27];
    const float* c2b    = (const float*)d_in[28];
    const float* c3W    = (const float*)d_in[29];
    const float* c3b    = (const float*)d_in[30];

    float* out = (float*)d_out;
    float* outConf = out;
    float* outFeat = out + MTOT;

    float *px, *pt, *pq, *pk, *pv, *pa, *pu1, *pu2;
    cudaGetSymbolAddress((void**)&px,  g_x);
    cudaGetSymbolAddress((void**)&pt,  g_t);
    cudaGetSymbolAddress((void**)&pq,  g_qb);
    cudaGetSymbolAddress((void**)&pk,  g_kb);
    cudaGetSymbolAddress((void**)&pv,  g_vb);
    cudaGetSymbolAddress((void**)&pa,  g_ab);
    cudaGetSymbolAddress((void**)&pu1, g_u1);
    cudaGetSymbolAddress((void**)&pu2, g_u2);

    cudaFuncSetAttribute(k_attn, cudaFuncAttributeMaxDynamicSharedMemorySize, ATTN_SMEM);

    const int GM = (MTOT + 63) / 64;  // 94

    k_init<<<(MTOT * CH + 255) / 256, 256>>>(corr, initW, initb);

    for (int i = 0; i < NLAYER; i++) {
        k_gemm<<<dim3(GM, 2), 256>>>(px, pcnW + i * CH * CH, pcnb + i * CH, pt, 128, 128, 0);
        k_bn<<<128, 256>>>(pt, pcng + i * CH, pcnbt + i * CH, 128);
        k_bnrelu<<<(MTOT * 128 + 255) / 256, 256>>>(pt, px, 128);

        k_gemm<<<dim3(GM, 2), 256>>>(px, qW + i * CH * CH, qb + i * CH, pq, 128, 128, 0);
        k_gemm<<<dim3(GM, 2), 256>>>(px, kW + i * CH * CH, kb + i * CH, pk, 128, 128, 0);
        k_gemm<<<dim3(GM, 2), 256>>>(px, vW + i * CH * CH, vb + i * CH, pv, 128, 128, 0);

        k_attn<<<dim3((NPTS + 63) / 64, BB), 256, ATTN_SMEM>>>(pq, pk, pv, src, tgt, pa);

        k_gemm<<<dim3(GM, 1), 256>>>(pa, m1W + i * 64 * 128, m1b + i * 64, pt, 128, 64, 0);
        k_bn<<<64, 256>>>(pt, m1g + i * 64, m1bt + i * 64, 64);
        k_bnrelu<<<(MTOT * 64 + 255) / 256, 256>>>(pt, pu1, 64);

        k_gemm<<<dim3(GM, 1), 256>>>(pu1, m2W + i * 64 * 64, m2b + i * 64, pt, 64, 64, 0);
        k_bn<<<64, 256>>>(pt, m2g + i * 64, m2bt + i * 64, 64);
        k_bnrelu<<<(MTOT * 64 + 255) / 256, 256>>>(pt, pu2, 64);

        k_gemm<<<dim3(GM, 2), 256>>>(pu2, m3W + i * 128 * 64, m3b + i * CH, px, 64, 128, 1);
    }

    k_final<<<(MTOT + 31) / 32, 256>>>(c1W, c1b, c2W, c2b, c3W, c3b, outConf, outFeat);
}